// round 11
// baseline (speedup 1.0000x reference)
#include <cuda_runtime.h>
#include <cstdint>

typedef unsigned long long u64;

#define DT_F      0.1f
#define NITERS    9               // int(1.0 // 0.1) == 9 in Python float semantics!
#define BATCH     64
#define NN        1024
#define NOBS      64
#define NACT      16
#define CPB       16              // CTAs per batch
#define ROWS_CTA  64              // rows per CTA (32 in regs + 32 in smem)
#define NCLUST    8               // groups
#define BPG       (BATCH / NCLUST)   // 8 batches per group
#define NTHREADS  288             // 8 compute warps + 1 gather warp

// y-exchange: 8-byte words = (tag<<32)|float_bits; y_t carries tag t+1, in buf[t&1].
__device__ u64 g_ybuf[2][BATCH][NN];

__global__ void ctrnn_init_kernel() {
    int i = blockIdx.x * blockDim.x + threadIdx.x;
    if (i < 2 * BATCH * NN) ((u64*)g_ybuf)[i] = 0ull;   // tag 0 = invalid
}

__device__ __forceinline__ void stcg64(u64* p, u64 v) {
    asm volatile("st.global.cg.u64 [%0], %1;" :: "l"(p), "l"(v) : "memory");
}
__device__ __forceinline__ void vld2g(const u64* p, u64& a, u64& b) {
    asm volatile("ld.global.cg.v2.u64 {%0,%1}, [%2];" : "=l"(a), "=l"(b) : "l"(p));
}

__device__ __forceinline__ void mbar_init(uint32_t a, uint32_t cnt) {
    asm volatile("mbarrier.init.shared.b64 [%0], %1;" :: "r"(a), "r"(cnt) : "memory");
}
__device__ __forceinline__ void mbar_expect_tx(uint32_t a, uint32_t bytes) {
    asm volatile("mbarrier.arrive.expect_tx.shared.b64 _, [%0], %1;" :: "r"(a), "r"(bytes) : "memory");
}
__device__ __forceinline__ void mbar_wait(uint32_t a, uint32_t parity) {
    asm volatile(
        "{\n\t.reg .pred P;\n\t"
        "W_%=:\n\t"
        "mbarrier.try_wait.parity.shared.b64 P, [%0], %1;\n\t"
        "@P bra.uni D_%=;\n\t"
        "bra.uni W_%=;\n\t"
        "D_%=:\n\t}"
        :: "r"(a), "r"(parity) : "memory");
}
__device__ __forceinline__ void bulk_g2s(uint32_t dst, const void* src, uint32_t bytes, uint32_t mbar) {
    asm volatile(
        "cp.async.bulk.shared::cta.global.mbarrier::complete_tx::bytes [%0], [%1], %2, [%3];"
        :: "r"(dst), "l"(src), "r"(bytes), "r"(mbar) : "memory");
}
__device__ __forceinline__ void issue_chunks(uint32_t dst, const char* gsrc,
                                             uint32_t bytes, uint32_t mbar) {
    asm volatile("fence.proxy.async.shared::cta;" ::: "memory");
    mbar_expect_tx(mbar, bytes);
    for (uint32_t c = 0; c < bytes; c += 32768)
        bulk_g2s(dst + c, gsrc + c, 32768, mbar);
}

#define NBAR_SYNC(id, cnt)   asm volatile("bar.sync %0, %1;"   :: "r"(id), "r"(cnt) : "memory")
#define NBAR_ARRIVE(id, cnt) asm volatile("bar.arrive %0, %1;" :: "r"(id), "r"(cnt) : "memory")

// SMEM layout (bytes)
#define S1_OFF    0               // smem W half (32 rows)          131072
#define S0_OFF    131072          // staging (16 rows)               65536
#define YB_OFF    196608          // ysm[2][1024] floats              8192
#define P_OFF     204800          // P[6][64]                         1536
#define OBS_OFF   206336          // obs_s[64]                         256
#define RED_OFF   206592          // red_s[12]                          48
#define BAR_OFF   206640          // wbar0,wbar1                        16
#define SMEM_BYTES 206656

__global__ __launch_bounds__(NTHREADS, 1)
void ctrnn_kernel(const float* __restrict__ obs,  const float* __restrict__ v0,
                  const float* __restrict__ tau,  const float* __restrict__ gain,
                  const float* __restrict__ bias, const float* __restrict__ W,
                  const float* __restrict__ mask, const float* __restrict__ E,
                  const float* __restrict__ D,    float* __restrict__ out)
{
    extern __shared__ char sm[];
    float4* S1f4  = (float4*)(sm + S1_OFF);    // 32 rows x 256 float4
    float4* S0f4  = (float4*)(sm + S0_OFF);    // 16 rows x 256 float4
    float*  YB    = (float*)(sm + YB_OFF);     // ysm[2][1024]
    float*  P     = (float*)(sm + P_OFF);      // [6][64]
    float*  obs_s = (float*)(sm + OBS_OFF);
    float*  red_s = (float*)(sm + RED_OFF);

    const int tid  = threadIdx.x;
    const int warp = tid >> 5;
    const int lane = tid & 31;
    const int group = blockIdx.x >> 4;
    const int cig   = blockIdx.x & 15;
    const int base  = cig * ROWS_CTA;

    const uint32_t mbar0 = (uint32_t)__cvta_generic_to_shared(sm + BAR_OFF);
    const uint32_t mbar1 = mbar0 + 8;
    const uint32_t S0a   = (uint32_t)__cvta_generic_to_shared(S0f4);
    const uint32_t S1a   = (uint32_t)__cvta_generic_to_shared(S1f4);

    if (tid == 0) {
        mbar_init(mbar0, 1);
        mbar_init(mbar1, 1);
        asm volatile("fence.proxy.async.shared::cta;" ::: "memory");
    }
    __syncthreads();
    if (tid == 0) {
        const char* g = (const char*)(W + ((size_t)(group * BPG) * NN + base) * NN);
        issue_chunks(S0a, g, 65536, mbar0);      // part1 of batch 0
    }

    float4 Wreg[4][8];   // compute warps: 4 register rows x 8 float4-chunks
    int li0 = 0, li1 = 0;

    for (int bi = 0; bi < BPG; bi++) {
        const int b = group * BPG + bi;
        const char* gW = (const char*)(W + ((size_t)b * NN + base) * NN);

        // ---------- W: part1 -> registers (warps 0-3) ----------
        mbar_wait(mbar0, (uint32_t)(li0 & 1)); li0++;
        if (warp < 4) {
            #pragma unroll
            for (int r = 0; r < 4; r++)
                #pragma unroll
                for (int j = 0; j < 8; j++)
                    Wreg[r][j] = S0f4[(warp * 4 + r) * 256 + j * 32 + lane];
        }
        __syncthreads();
        if (tid == 0) {
            issue_chunks(S0a, gW + 65536, 65536, mbar0);     // part2
            issue_chunks(S1a, gW + 131072, 131072, mbar1);   // smem half
        }

        // ---------- prologue: params + publish y0 (tag 1) ----------
        if (tid < NOBS) obs_s[tid] = obs[(size_t)b * NOBS + tid];
        __syncthreads();
        if (tid < ROWS_CTA) {
            const int n = base + tid;
            const size_t o = (size_t)b * NN + n;
            float vv = v0[o], gg = gain[o], bb = bias[o], mm = mask[o];
            P[0 * 64 + tid] = vv;
            P[1 * 64 + tid] = DT_F / tau[o];
            P[3 * 64 + tid] = gg;
            P[4 * 64 + tid] = bb;
            P[5 * 64 + tid] = mm;
            const float* Er = E + o * NOBS;
            float s = 0.f;
            #pragma unroll
            for (int q = 0; q < NOBS; q++) s += Er[q] * obs_s[q];
            P[2 * 64 + tid] = s;
            float y0 = tanhf(gg * (vv + bb)) * mm;
            stcg64(&g_ybuf[0][b][n], ((u64)1 << 32) | (u64)__float_as_uint(y0));
        }

        // ---------- W: part2 -> registers (warps 4-7); smem half ready ----------
        mbar_wait(mbar0, (uint32_t)(li0 & 1)); li0++;
        if (warp >= 4 && warp < 8) {
            #pragma unroll
            for (int r = 0; r < 4; r++)
                #pragma unroll
                for (int j = 0; j < 8; j++)
                    Wreg[r][j] = S0f4[((warp - 4) * 4 + r) * 256 + j * 32 + lane];
        }
        mbar_wait(mbar1, (uint32_t)(li1 & 1)); li1++;
        __syncthreads();                                     // S0 free, S1 + P ready
        if (tid == 0 && bi + 1 < BPG) {
            const char* gn = (const char*)(W + ((size_t)(b + 1) * NN + base) * NN);
            issue_chunks(S0a, gn, 65536, mbar0);             // next part1
        }

        // ================== iterations: warp-specialized ==================
        if (warp == 8) {
            // -------- gather warp: settle y(t-1) into ysm[(t-1)&1], hand off --------
            const int i0 = lane * 2;
            for (int t = 1; t <= NITERS + 1; t++) {
                const u64* src = &g_ybuf[(t - 1) & 1][b][0];
                const unsigned exp = (unsigned)t;
                u64 xa[16], xb[16];
                #pragma unroll
                for (int k = 0; k < 16; k++)
                    vld2g(src + i0 + 64 * k, xa[k], xb[k]);
                #pragma unroll
                for (int k = 0; k < 16; k++)
                    while ((unsigned)(xa[k] >> 32) != exp ||
                           (unsigned)(xb[k] >> 32) != exp) {
                        __nanosleep(20);
                        vld2g(src + i0 + 64 * k, xa[k], xb[k]);
                    }
                float* ys = YB + ((t - 1) & 1) * NN;
                #pragma unroll
                for (int k = 0; k < 16; k++) {
                    float2 v2v = make_float2(
                        __uint_as_float((unsigned)(xa[k] & 0xffffffffu)),
                        __uint_as_float((unsigned)(xb[k] & 0xffffffffu)));
                    *(float2*)(ys + i0 + 64 * k) = v2v;
                }
                NBAR_ARRIVE(1 + (t & 1), NTHREADS);
            }
        } else {
            // -------- compute warps --------
            const float4* S1w = S1f4 + (size_t)(warp * 4) * 256;
            for (int t = 1; t <= NITERS; t++) {
                NBAR_SYNC(1 + (t & 1), NTHREADS);            // y(t-1) ready in ysm
                const float4* Y4 = (const float4*)(YB + ((t - 1) & 1) * NN);

                float ar0 = 0.f, ar1 = 0.f, ar2 = 0.f, ar3 = 0.f;
                float as0 = 0.f, as1 = 0.f, as2 = 0.f, as3 = 0.f;
                #pragma unroll
                for (int j = 0; j < 8; j++) {
                    const float4 y4 = Y4[j * 32 + lane];
                    float4 w;
                    w = Wreg[0][j];                   ar0 += w.x*y4.x; ar0 += w.y*y4.y; ar0 += w.z*y4.z; ar0 += w.w*y4.w;
                    w = Wreg[1][j];                   ar1 += w.x*y4.x; ar1 += w.y*y4.y; ar1 += w.z*y4.z; ar1 += w.w*y4.w;
                    w = Wreg[2][j];                   ar2 += w.x*y4.x; ar2 += w.y*y4.y; ar2 += w.z*y4.z; ar2 += w.w*y4.w;
                    w = Wreg[3][j];                   ar3 += w.x*y4.x; ar3 += w.y*y4.y; ar3 += w.z*y4.z; ar3 += w.w*y4.w;
                    w = S1w[0 * 256 + j * 32 + lane]; as0 += w.x*y4.x; as0 += w.y*y4.y; as0 += w.z*y4.z; as0 += w.w*y4.w;
                    w = S1w[1 * 256 + j * 32 + lane]; as1 += w.x*y4.x; as1 += w.y*y4.y; as1 += w.z*y4.z; as1 += w.w*y4.w;
                    w = S1w[2 * 256 + j * 32 + lane]; as2 += w.x*y4.x; as2 += w.y*y4.y; as2 += w.z*y4.z; as2 += w.w*y4.w;
                    w = S1w[3 * 256 + j * 32 + lane]; as3 += w.x*y4.x; as3 += w.y*y4.y; as3 += w.z*y4.z; as3 += w.w*y4.w;
                }
                #pragma unroll
                for (int off = 16; off > 0; off >>= 1) {
                    ar0 += __shfl_xor_sync(0xffffffffu, ar0, off);
                    ar1 += __shfl_xor_sync(0xffffffffu, ar1, off);
                    ar2 += __shfl_xor_sync(0xffffffffu, ar2, off);
                    ar3 += __shfl_xor_sync(0xffffffffu, ar3, off);
                    as0 += __shfl_xor_sync(0xffffffffu, as0, off);
                    as1 += __shfl_xor_sync(0xffffffffu, as1, off);
                    as2 += __shfl_xor_sync(0xffffffffu, as2, off);
                    as3 += __shfl_xor_sync(0xffffffffu, as3, off);
                }

                if (lane < 8) {
                    float dot;
                    int rloc;
                    if (lane < 4) {
                        dot  = (lane == 0) ? ar0 : (lane == 1) ? ar1 : (lane == 2) ? ar2 : ar3;
                        rloc = warp * 4 + lane;
                    } else {
                        dot  = (lane == 4) ? as0 : (lane == 5) ? as1 : (lane == 6) ? as2 : as3;
                        rloc = 32 + warp * 4 + (lane - 4);
                    }
                    float v  = P[0 * 64 + rloc];
                    float nv = (v + P[1 * 64 + rloc] * (dot + P[2 * 64 + rloc] - v)) * P[5 * 64 + rloc];
                    P[0 * 64 + rloc] = nv;
                    float ov = (t < NITERS)
                        ? tanhf(P[3 * 64 + rloc] * (nv + P[4 * 64 + rloc])) * P[5 * 64 + rloc]
                        : nv;
                    stcg64(&g_ybuf[t & 1][b][base + rloc],
                           ((u64)(unsigned)(t + 1) << 32) | (u64)__float_as_uint(ov));
                }
            }
            // decode handoff: final v settled by gather phase t = NITERS+1 into ysm[1]
            NBAR_SYNC(1 + ((NITERS + 1) & 1), NTHREADS);
        }

        // ---------- decode (all 9 warps): each CTA produces one action ----------
        {
            const float* vf = YB + ((NITERS) & 1) * NN;      // ysm[(10-1)&1] = ysm[1]
            const float* Dr = D + ((size_t)b * NACT + cig) * NN;
            float p = 0.f;
            for (int i = tid; i < NN; i += NTHREADS) p += Dr[i] * vf[i];
            #pragma unroll
            for (int off = 16; off > 0; off >>= 1)
                p += __shfl_xor_sync(0xffffffffu, p, off);
            if (lane == 0) red_s[warp] = p;
            __syncthreads();
            if (tid == 0) {
                float s = 0.f;
                #pragma unroll
                for (int j = 0; j < 9; j++) s += red_s[j];
                out[b * NACT + cig] = s;
            }
        }
        __syncthreads();   // ysm / P / red_s free for next batch
    }
}

extern "C" void kernel_launch(void* const* d_in, const int* in_sizes, int n_in,
                              void* d_out, int out_size) {
    const float* obs  = (const float*)d_in[0];
    const float* v0   = (const float*)d_in[1];
    const float* tau  = (const float*)d_in[2];
    const float* gain = (const float*)d_in[3];
    const float* bias = (const float*)d_in[4];
    const float* W    = (const float*)d_in[5];
    const float* mask = (const float*)d_in[6];
    const float* E    = (const float*)d_in[7];
    const float* D    = (const float*)d_in[8];
    float* out = (float*)d_out;

    cudaFuncSetAttribute(ctrnn_kernel,
                         cudaFuncAttributeMaxDynamicSharedMemorySize, SMEM_BYTES);

    // reset exchange tags each launch (tag-freshness invariant, graph-replay safe)
    ctrnn_init_kernel<<<(2 * BATCH * NN + 255) / 256, 256>>>();

    // 128 CTAs = 8 groups x 16; ~202 KB smem each -> 1 CTA/SM, all co-resident
    ctrnn_kernel<<<NCLUST * CPB, NTHREADS, SMEM_BYTES>>>(
        obs, v0, tau, gain, bias, W, mask, E, D, out);
}

// round 12
// speedup vs baseline: 1.2320x; 1.2320x over previous
#include <cuda_runtime.h>
#include <cstdint>

typedef unsigned long long u64;

#define DT_F      0.1f
#define NITERS    9               // int(1.0 // 0.1) == 9 in Python float semantics!
#define BATCH     64
#define NN        1024
#define NOBS      64
#define NACT      16
#define CPB       16              // CTAs per batch
#define ROWS_CTA  64              // rows per CTA
#define NCLUST    8               // groups
#define BPG       (BATCH / NCLUST)
#define NTHREADS  256             // 7 compute warps + 1 gather warp
#define GW        7               // gather warp id

// y-exchange: 8-byte words = (tag<<32)|float_bits; y_t carries tag t+1, in buf[t&1].
__device__ u64 g_ybuf[2][BATCH][NN];

__global__ void ctrnn_init_kernel() {
    int i = blockIdx.x * blockDim.x + threadIdx.x;
    if (i < 2 * BATCH * NN) ((u64*)g_ybuf)[i] = 0ull;   // tag 0 = invalid
}

__device__ __forceinline__ void stcg64(u64* p, u64 v) {
    asm volatile("st.global.cg.u64 [%0], %1;" :: "l"(p), "l"(v) : "memory");
}
__device__ __forceinline__ void vld2g(const u64* p, u64& a, u64& b) {
    asm volatile("ld.global.cg.v2.u64 {%0,%1}, [%2];" : "=l"(a), "=l"(b) : "l"(p));
}

__device__ __forceinline__ void mbar_init(uint32_t a, uint32_t cnt) {
    asm volatile("mbarrier.init.shared.b64 [%0], %1;" :: "r"(a), "r"(cnt) : "memory");
}
__device__ __forceinline__ void mbar_expect_tx(uint32_t a, uint32_t bytes) {
    asm volatile("mbarrier.arrive.expect_tx.shared.b64 _, [%0], %1;" :: "r"(a), "r"(bytes) : "memory");
}
__device__ __forceinline__ void mbar_wait(uint32_t a, uint32_t parity) {
    asm volatile(
        "{\n\t.reg .pred P;\n\t"
        "W_%=:\n\t"
        "mbarrier.try_wait.parity.shared.b64 P, [%0], %1;\n\t"
        "@P bra.uni D_%=;\n\t"
        "bra.uni W_%=;\n\t"
        "D_%=:\n\t}"
        :: "r"(a), "r"(parity) : "memory");
}
__device__ __forceinline__ void bulk_g2s(uint32_t dst, const void* src, uint32_t bytes, uint32_t mbar) {
    asm volatile(
        "cp.async.bulk.shared::cta.global.mbarrier::complete_tx::bytes [%0], [%1], %2, [%3];"
        :: "r"(dst), "l"(src), "r"(bytes), "r"(mbar) : "memory");
}
__device__ __forceinline__ void issue_chunks(uint32_t dst, const char* gsrc,
                                             uint32_t bytes, uint32_t mbar) {
    asm volatile("fence.proxy.async.shared::cta;" ::: "memory");
    mbar_expect_tx(mbar, bytes);
    for (uint32_t c = 0; c < bytes; c += 32768) {
        uint32_t n = (bytes - c < 32768u) ? (bytes - c) : 32768u;
        bulk_g2s(dst + c, gsrc + c, n, mbar);
    }
}

#define NBAR_SYNC(id)   asm volatile("bar.sync %0, %1;"   :: "r"(id), "r"(NTHREADS) : "memory")
#define NBAR_ARRIVE(id) asm volatile("bar.arrive %0, %1;" :: "r"(id), "r"(NTHREADS) : "memory")

// SMEM layout (bytes):
//   S1: W smem rows 28..63 (36 rows)   [0, 147456)
//   S0: staging (<=16 rows)            [147456, 212992)
//   ysm[2][1024]                       [212992, 221184)
//   P[6][64]                           [221184, 222720)
//   obs_s[64]                          [222720, 222976)
//   red_s[8]                           [222976, 223008)
//   wbar0, wbar1                       [223008, 223024)
#define S1_OFF    0
#define S0_OFF    147456
#define YB_OFF    212992
#define P_OFF     221184
#define OBS_OFF   222720
#define RED_OFF   222976
#define BAR_OFF   223008
#define SMEM_BYTES 223024

__global__ __launch_bounds__(NTHREADS, 1)
void ctrnn_kernel(const float* __restrict__ obs,  const float* __restrict__ v0,
                  const float* __restrict__ tau,  const float* __restrict__ gain,
                  const float* __restrict__ bias, const float* __restrict__ W,
                  const float* __restrict__ mask, const float* __restrict__ E,
                  const float* __restrict__ D,    float* __restrict__ out)
{
    extern __shared__ char sm[];
    float4* S1f4  = (float4*)(sm + S1_OFF);    // 36 rows x 256 float4 (rows 28..63)
    float4* S0f4  = (float4*)(sm + S0_OFF);    // staging, up to 16 rows
    float*  YB    = (float*)(sm + YB_OFF);     // ysm[2][1024]
    float*  P     = (float*)(sm + P_OFF);      // [6][64]
    float*  obs_s = (float*)(sm + OBS_OFF);
    float*  red_s = (float*)(sm + RED_OFF);

    const int tid  = threadIdx.x;
    const int warp = tid >> 5;
    const int lane = tid & 31;
    const int group = blockIdx.x >> 4;
    const int cig   = blockIdx.x & 15;
    const int base  = cig * ROWS_CTA;

    const uint32_t mbar0 = (uint32_t)__cvta_generic_to_shared(sm + BAR_OFF);
    const uint32_t mbar1 = mbar0 + 8;
    const uint32_t S0a   = (uint32_t)__cvta_generic_to_shared(S0f4);
    const uint32_t S1a   = (uint32_t)__cvta_generic_to_shared(S1f4);

    if (tid == 0) {
        mbar_init(mbar0, 1);
        mbar_init(mbar1, 1);
        asm volatile("fence.proxy.async.shared::cta;" ::: "memory");
    }
    __syncthreads();
    if (tid == 0) {
        // wave1 of batch 0: global W rows 0..15 of this CTA's chunk
        const char* g = (const char*)(W + ((size_t)(group * BPG) * NN + base) * NN);
        issue_chunks(S0a, g, 65536, mbar0);
    }

    float4 Wreg[4][8];   // compute warps: reg rows 4w..4w+3, 8 float4-chunks each
    int li0 = 0, li1 = 0;

    for (int bi = 0; bi < BPG; bi++) {
        const int b = group * BPG + bi;
        const char* gW = (const char*)(W + ((size_t)b * NN + base) * NN);

        // ---------- wave1 (rows 0..15) -> registers of warps 0..3 ----------
        mbar_wait(mbar0, (uint32_t)(li0 & 1)); li0++;
        if (warp < 4) {
            #pragma unroll
            for (int r = 0; r < 4; r++)
                #pragma unroll
                for (int j = 0; j < 8; j++)
                    Wreg[r][j] = S0f4[(warp * 4 + r) * 256 + j * 32 + lane];
        }
        __syncthreads();   // S0 free
        if (tid == 0) {
            issue_chunks(S0a, gW + 16 * 4096, 12 * 4096, mbar0);   // wave2: rows 16..27
            issue_chunks(S1a, gW + 28 * 4096, 36 * 4096, mbar1);   // smem half: rows 28..63
        }

        // ---------- prologue: params + publish y0 (tag 1) ----------
        if (tid < NOBS) obs_s[tid] = obs[(size_t)b * NOBS + tid];
        __syncthreads();
        if (tid < ROWS_CTA) {
            const int n = base + tid;
            const size_t o = (size_t)b * NN + n;
            float vv = v0[o], gg = gain[o], bb = bias[o], mm = mask[o];
            P[0 * 64 + tid] = vv;
            P[1 * 64 + tid] = DT_F / tau[o];
            P[3 * 64 + tid] = gg;
            P[4 * 64 + tid] = bb;
            P[5 * 64 + tid] = mm;
            const float* Er = E + o * NOBS;
            float s = 0.f;
            #pragma unroll
            for (int q = 0; q < NOBS; q++) s += Er[q] * obs_s[q];
            P[2 * 64 + tid] = s;
            float y0 = tanhf(gg * (vv + bb)) * mm;
            stcg64(&g_ybuf[0][b][n], ((u64)1 << 32) | (u64)__float_as_uint(y0));
        }

        // ---------- wave2 (rows 16..27) -> registers of warps 4..6 ----------
        mbar_wait(mbar0, (uint32_t)(li0 & 1)); li0++;
        if (warp >= 4 && warp < GW) {
            #pragma unroll
            for (int r = 0; r < 4; r++)
                #pragma unroll
                for (int j = 0; j < 8; j++)
                    Wreg[r][j] = S0f4[(warp * 4 - 16 + r) * 256 + j * 32 + lane];
        }
        mbar_wait(mbar1, (uint32_t)(li1 & 1)); li1++;
        __syncthreads();   // S0 free, S1 + P ready
        if (tid == 0 && bi + 1 < BPG) {
            const char* gn = (const char*)(W + ((size_t)(b + 1) * NN + base) * NN);
            issue_chunks(S0a, gn, 65536, mbar0);   // next batch wave1, flies during iters
        }

        // ================== iterations: warp-specialized ==================
        if (warp == GW) {
            // ---- gather warp: settle y(t-1) into ysm, compute+publish row 63 ----
            const int i0 = lane * 2;
            for (int t = 1; t <= NITERS + 1; t++) {
                const u64* src = &g_ybuf[(t - 1) & 1][b][0];
                const unsigned exp = (unsigned)t;
                u64 xa[16], xb[16];
                #pragma unroll
                for (int k = 0; k < 16; k++)
                    vld2g(src + i0 + 64 * k, xa[k], xb[k]);
                #pragma unroll
                for (int k = 0; k < 16; k++)
                    while ((unsigned)(xa[k] >> 32) != exp ||
                           (unsigned)(xb[k] >> 32) != exp) {
                        __nanosleep(20);
                        vld2g(src + i0 + 64 * k, xa[k], xb[k]);
                    }
                float* ys = YB + ((t - 1) & 1) * NN;
                #pragma unroll
                for (int k = 0; k < 16; k++) {
                    float2 v2v = make_float2(
                        __uint_as_float((unsigned)(xa[k] & 0xffffffffu)),
                        __uint_as_float((unsigned)(xb[k] & 0xffffffffu)));
                    *(float2*)(ys + i0 + 64 * k) = v2v;
                }
                __syncwarp();
                NBAR_ARRIVE(1 + (t & 1));          // release compute warps

                if (t <= NITERS) {
                    // compute + publish row 63 (S1 row 35) from local ysm
                    const float4* Y4 = (const float4*)ys;
                    const float4* Wr = S1f4 + 35 * 256;
                    float acc = 0.f;
                    #pragma unroll
                    for (int j = 0; j < 8; j++) {
                        const float4 y4 = Y4[j * 32 + lane];
                        const float4 w  = Wr[j * 32 + lane];
                        acc += w.x*y4.x; acc += w.y*y4.y; acc += w.z*y4.z; acc += w.w*y4.w;
                    }
                    #pragma unroll
                    for (int off = 16; off > 0; off >>= 1)
                        acc += __shfl_xor_sync(0xffffffffu, acc, off);
                    if (lane == 0) {
                        float v  = P[0 * 64 + 63];
                        float nv = (v + P[1 * 64 + 63] * (acc + P[2 * 64 + 63] - v)) * P[5 * 64 + 63];
                        P[0 * 64 + 63] = nv;
                        float ov = (t < NITERS)
                            ? tanhf(P[3 * 64 + 63] * (nv + P[4 * 64 + 63])) * P[5 * 64 + 63]
                            : nv;
                        stcg64(&g_ybuf[t & 1][b][base + 63],
                               ((u64)(unsigned)(t + 1) << 32) | (u64)__float_as_uint(ov));
                    }
                }
            }
        } else {
            // ---- compute warps 0..6: 4 reg rows + 5 smem rows each ----
            const float4* S1w = S1f4 + (size_t)(warp * 5) * 256;   // rows 28+5w..32+5w
            for (int t = 1; t <= NITERS; t++) {
                NBAR_SYNC(1 + (t & 1));            // y(t-1) ready in ysm
                const float4* Y4 = (const float4*)(YB + ((t - 1) & 1) * NN);

                float ar0 = 0.f, ar1 = 0.f, ar2 = 0.f, ar3 = 0.f;
                float as0 = 0.f, as1 = 0.f, as2 = 0.f, as3 = 0.f, as4 = 0.f;
                #pragma unroll
                for (int j = 0; j < 8; j++) {
                    const float4 y4 = Y4[j * 32 + lane];
                    float4 w;
                    w = Wreg[0][j];                   ar0 += w.x*y4.x; ar0 += w.y*y4.y; ar0 += w.z*y4.z; ar0 += w.w*y4.w;
                    w = Wreg[1][j];                   ar1 += w.x*y4.x; ar1 += w.y*y4.y; ar1 += w.z*y4.z; ar1 += w.w*y4.w;
                    w = Wreg[2][j];                   ar2 += w.x*y4.x; ar2 += w.y*y4.y; ar2 += w.z*y4.z; ar2 += w.w*y4.w;
                    w = Wreg[3][j];                   ar3 += w.x*y4.x; ar3 += w.y*y4.y; ar3 += w.z*y4.z; ar3 += w.w*y4.w;
                    w = S1w[0 * 256 + j * 32 + lane]; as0 += w.x*y4.x; as0 += w.y*y4.y; as0 += w.z*y4.z; as0 += w.w*y4.w;
                    w = S1w[1 * 256 + j * 32 + lane]; as1 += w.x*y4.x; as1 += w.y*y4.y; as1 += w.z*y4.z; as1 += w.w*y4.w;
                    w = S1w[2 * 256 + j * 32 + lane]; as2 += w.x*y4.x; as2 += w.y*y4.y; as2 += w.z*y4.z; as2 += w.w*y4.w;
                    w = S1w[3 * 256 + j * 32 + lane]; as3 += w.x*y4.x; as3 += w.y*y4.y; as3 += w.z*y4.z; as3 += w.w*y4.w;
                    w = S1w[4 * 256 + j * 32 + lane]; as4 += w.x*y4.x; as4 += w.y*y4.y; as4 += w.z*y4.z; as4 += w.w*y4.w;
                }
                #pragma unroll
                for (int off = 16; off > 0; off >>= 1) {
                    ar0 += __shfl_xor_sync(0xffffffffu, ar0, off);
                    ar1 += __shfl_xor_sync(0xffffffffu, ar1, off);
                    ar2 += __shfl_xor_sync(0xffffffffu, ar2, off);
                    ar3 += __shfl_xor_sync(0xffffffffu, ar3, off);
                    as0 += __shfl_xor_sync(0xffffffffu, as0, off);
                    as1 += __shfl_xor_sync(0xffffffffu, as1, off);
                    as2 += __shfl_xor_sync(0xffffffffu, as2, off);
                    as3 += __shfl_xor_sync(0xffffffffu, as3, off);
                    as4 += __shfl_xor_sync(0xffffffffu, as4, off);
                }

                if (lane < 9) {
                    float dot;
                    int rloc;
                    if (lane < 4) {
                        dot  = (lane == 0) ? ar0 : (lane == 1) ? ar1 : (lane == 2) ? ar2 : ar3;
                        rloc = warp * 4 + lane;
                    } else {
                        dot  = (lane == 4) ? as0 : (lane == 5) ? as1 : (lane == 6) ? as2
                             : (lane == 7) ? as3 : as4;
                        rloc = 28 + warp * 5 + (lane - 4);
                    }
                    float v  = P[0 * 64 + rloc];
                    float nv = (v + P[1 * 64 + rloc] * (dot + P[2 * 64 + rloc] - v)) * P[5 * 64 + rloc];
                    P[0 * 64 + rloc] = nv;
                    float ov = (t < NITERS)
                        ? tanhf(P[3 * 64 + rloc] * (nv + P[4 * 64 + rloc])) * P[5 * 64 + rloc]
                        : nv;
                    stcg64(&g_ybuf[t & 1][b][base + rloc],
                           ((u64)(unsigned)(t + 1) << 32) | (u64)__float_as_uint(ov));
                }
            }
            // final handoff: gather phase t=10 settles final v into ysm[1]
            NBAR_SYNC(1 + ((NITERS + 1) & 1));
        }

        // ---------- decode (all 8 warps): each CTA produces one action ----------
        {
            const float* vf = YB + (NITERS & 1) * NN;   // ysm[1] = final v
            const float* Dr = D + ((size_t)b * NACT + cig) * NN;
            float p = 0.f;
            for (int i = tid; i < NN; i += NTHREADS) p += Dr[i] * vf[i];
            #pragma unroll
            for (int off = 16; off > 0; off >>= 1)
                p += __shfl_xor_sync(0xffffffffu, p, off);
            if (lane == 0) red_s[warp] = p;
            __syncthreads();
            if (tid == 0) {
                float s = 0.f;
                #pragma unroll
                for (int j = 0; j < 8; j++) s += red_s[j];
                out[b * NACT + cig] = s;
            }
        }
        __syncthreads();   // ysm / P / red_s free for next batch
    }
}

extern "C" void kernel_launch(void* const* d_in, const int* in_sizes, int n_in,
                              void* d_out, int out_size) {
    const float* obs  = (const float*)d_in[0];
    const float* v0   = (const float*)d_in[1];
    const float* tau  = (const float*)d_in[2];
    const float* gain = (const float*)d_in[3];
    const float* bias = (const float*)d_in[4];
    const float* W    = (const float*)d_in[5];
    const float* mask = (const float*)d_in[6];
    const float* E    = (const float*)d_in[7];
    const float* D    = (const float*)d_in[8];
    float* out = (float*)d_out;

    cudaFuncSetAttribute(ctrnn_kernel,
                         cudaFuncAttributeMaxDynamicSharedMemorySize, SMEM_BYTES);

    // reset exchange tags each launch (tag-freshness invariant, graph-replay safe)
    ctrnn_init_kernel<<<(2 * BATCH * NN + 255) / 256, 256>>>();

    // 128 CTAs = 8 groups x 16; ~218 KB smem each -> 1 CTA/SM, all co-resident
    ctrnn_kernel<<<NCLUST * CPB, NTHREADS, SMEM_BYTES>>>(
        obs, v0, tau, gain, bias, W, mask, E, D, out);
}

// round 13
// speedup vs baseline: 3.2241x; 2.6170x over previous
#include <cuda_runtime.h>
#include <cstdint>

typedef unsigned long long u64;

#define DT_F      0.1f
#define NITERS    9               // int(1.0 // 0.1) == 9 in Python float semantics!
#define BATCH     64
#define NN        1024
#define NOBS      64
#define NACT      16
#define GROUPS    8               // groups of 16 CTAs; one batch at a time per group
#define CPB       16              // CTAs per batch
#define ROWS_CTA  64              // rows per CTA (32 in regs + 32 in smem)
#define BPG       (BATCH / GROUPS)   // 8 batches per group
#define NTHREADS  256

// y-exchange: 8-byte words = (tag<<32)|float_bits; y_t carries tag t+1, in buf[t&1].
__device__ u64 g_ybuf[2][BATCH][NN];

__global__ void ctrnn_init_kernel() {
    int i = blockIdx.x * blockDim.x + threadIdx.x;
    if (i < 2 * BATCH * NN) ((u64*)g_ybuf)[i] = 0ull;   // tag 0 = invalid
}

__device__ __forceinline__ u64 ldcg64(const u64* p) {
    u64 v;
    asm volatile("ld.global.cg.u64 %0, [%1];" : "=l"(v) : "l"(p));
    return v;
}
__device__ __forceinline__ void stcg64(u64* p, u64 v) {
    asm volatile("st.global.cg.u64 [%0], %1;" :: "l"(p), "l"(v) : "memory");
}

// gather 1024 tagged words (4/thread, strided 256).
// PARALLEL retry: every round re-issues ALL stale words concurrently, so a
// round costs one L2 latency regardless of how many words are stale
// (the old serial per-word spin chains cost up to 4 latencies).
__device__ __forceinline__ void settle4(const u64* src, unsigned exp, float* y_s, int tid) {
    u64 r0 = ldcg64(src + tid);
    u64 r1 = ldcg64(src + tid + 256);
    u64 r2 = ldcg64(src + tid + 512);
    u64 r3 = ldcg64(src + tid + 768);
    for (;;) {
        const bool s0 = (unsigned)(r0 >> 32) != exp;
        const bool s1 = (unsigned)(r1 >> 32) != exp;
        const bool s2 = (unsigned)(r2 >> 32) != exp;
        const bool s3 = (unsigned)(r3 >> 32) != exp;
        if (!(s0 | s1 | s2 | s3)) break;
        __nanosleep(30);
        if (s0) r0 = ldcg64(src + tid);
        if (s1) r1 = ldcg64(src + tid + 256);
        if (s2) r2 = ldcg64(src + tid + 512);
        if (s3) r3 = ldcg64(src + tid + 768);
    }
    y_s[tid]       = __uint_as_float((unsigned)(r0 & 0xffffffffu));
    y_s[tid + 256] = __uint_as_float((unsigned)(r1 & 0xffffffffu));
    y_s[tid + 512] = __uint_as_float((unsigned)(r2 & 0xffffffffu));
    y_s[tid + 768] = __uint_as_float((unsigned)(r3 & 0xffffffffu));
}

__device__ __forceinline__ void mbar_init(uint32_t a, uint32_t cnt) {
    asm volatile("mbarrier.init.shared.b64 [%0], %1;" :: "r"(a), "r"(cnt) : "memory");
}
__device__ __forceinline__ void mbar_expect_tx(uint32_t a, uint32_t bytes) {
    asm volatile("mbarrier.arrive.expect_tx.shared.b64 _, [%0], %1;" :: "r"(a), "r"(bytes) : "memory");
}
__device__ __forceinline__ void mbar_wait(uint32_t a, uint32_t parity) {
    asm volatile(
        "{\n\t.reg .pred P;\n\t"
        "W_%=:\n\t"
        "mbarrier.try_wait.parity.shared.b64 P, [%0], %1;\n\t"
        "@P bra.uni D_%=;\n\t"
        "bra.uni W_%=;\n\t"
        "D_%=:\n\t}"
        :: "r"(a), "r"(parity) : "memory");
}
__device__ __forceinline__ void bulk_g2s(uint32_t dst, const void* src, uint32_t bytes, uint32_t mbar) {
    asm volatile(
        "cp.async.bulk.shared::cta.global.mbarrier::complete_tx::bytes [%0], [%1], %2, [%3];"
        :: "r"(dst), "l"(src), "r"(bytes), "r"(mbar) : "memory");
}
__device__ __forceinline__ void issue_chunks(uint32_t dst, const char* gsrc,
                                             uint32_t bytes, uint32_t mbar) {
    asm volatile("fence.proxy.async.shared::cta;" ::: "memory");
    mbar_expect_tx(mbar, bytes);
    for (uint32_t c = 0; c < bytes; c += 32768)
        bulk_g2s(dst + c, gsrc + c, 32768, mbar);
}

// SMEM layout (bytes):
//   S1 (smem W half, 32 rows)   : [0, 131072)
//   S0 (staging, 16 rows)       : [131072, 196608)
//   y_s[2][1024]                : [196608, 204800)
//   P[6][64]                    : [204800, 206336)
//   obs_s[64]                   : [206336, 206592)
//   red_s[8]                    : [206592, 206624)
//   mbar0, mbar1                : [206624, 206640)
#define S1_OFF    0
#define S0_OFF    131072
#define YS_OFF    196608
#define P_OFF     204800
#define OBS_OFF   206336
#define RED_OFF   206592
#define MB_OFF    206624
#define SMEM_BYTES 206640

__global__ __launch_bounds__(NTHREADS, 1)
void ctrnn_kernel(const float* __restrict__ obs,  const float* __restrict__ v0,
                  const float* __restrict__ tau,  const float* __restrict__ gain,
                  const float* __restrict__ bias, const float* __restrict__ W,
                  const float* __restrict__ mask, const float* __restrict__ E,
                  const float* __restrict__ D,    float* __restrict__ out)
{
    extern __shared__ char sm[];
    float4* S1f4  = (float4*)(sm + S1_OFF);    // 32 rows x 256 float4
    float4* S0f4  = (float4*)(sm + S0_OFF);    // 16 rows x 256 float4
    float*  y_s0  = (float*)(sm + YS_OFF);     // parity 0
    float*  y_s1  = y_s0 + NN;                 // parity 1
    float*  P     = (float*)(sm + P_OFF);      // [6][64]
    float*  obs_s = (float*)(sm + OBS_OFF);
    float*  red_s = (float*)(sm + RED_OFF);

    const int tid  = threadIdx.x;
    const int warp = tid >> 5;
    const int lane = tid & 31;
    const int group = blockIdx.x >> 4;        // /16
    const int cig   = blockIdx.x & 15;
    const int base  = cig * ROWS_CTA;         // first of this CTA's 64 rows

    const uint32_t mbar0 = (uint32_t)__cvta_generic_to_shared(sm + MB_OFF);
    const uint32_t mbar1 = mbar0 + 8;
    const uint32_t S0a   = (uint32_t)__cvta_generic_to_shared(S0f4);
    const uint32_t S1a   = (uint32_t)__cvta_generic_to_shared(S1f4);

    if (tid == 0) {
        mbar_init(mbar0, 1);
        mbar_init(mbar1, 1);
        asm volatile("fence.proxy.async.shared::cta;" ::: "memory");
    }
    __syncthreads();

    if (tid == 0) {
        const char* g = (const char*)(W + ((size_t)(group * BPG) * NN + base) * NN);
        issue_chunks(S0a, g, 65536, mbar0);          // part1 of batch 0
    }

    float4 Wreg[4][8];   // this warp's 4 register rows x 8 float4-chunks
    int li0 = 0, li1 = 0;

    for (int bi = 0; bi < BPG; bi++) {
        const int b = group * BPG + bi;
        const char* gW = (const char*)(W + ((size_t)b * NN + base) * NN);

        // ---------- batch start: assemble W ----------
        mbar_wait(mbar0, (uint32_t)(li0 & 1)); li0++;        // part1 in S0
        if (warp < 4) {   // warps 0-3 own reg rows 0-15
            #pragma unroll
            for (int r = 0; r < 4; r++)
                #pragma unroll
                for (int j = 0; j < 8; j++)
                    Wreg[r][j] = S0f4[(warp * 4 + r) * 256 + j * 32 + lane];
        }
        __syncthreads();                                     // S0 free
        if (tid == 0) {
            issue_chunks(S0a, gW + 65536, 65536, mbar0);     // part2
            issue_chunks(S1a, gW + 131072, 131072, mbar1);   // smem half
        }

        // ---------- prologue (overlaps TMA) ----------
        if (tid < NOBS) obs_s[tid] = obs[(size_t)b * NOBS + tid];
        __syncthreads();
        if (tid < ROWS_CTA) {
            const int n = base + tid;
            const size_t o = (size_t)b * NN + n;
            float vv = v0[o], gg = gain[o], bb = bias[o], mm = mask[o];
            P[0 * 64 + tid] = vv;
            P[1 * 64 + tid] = DT_F / tau[o];
            P[3 * 64 + tid] = gg;
            P[4 * 64 + tid] = bb;
            P[5 * 64 + tid] = mm;
            const float* Er = E + o * NOBS;
            float s = 0.f;
            #pragma unroll
            for (int q = 0; q < NOBS; q++) s += Er[q] * obs_s[q];
            P[2 * 64 + tid] = s;
            float y0 = tanhf(gg * (vv + bb)) * mm;
            stcg64(&g_ybuf[0][b][n], ((u64)1 << 32) | (u64)__float_as_uint(y0));
        }

        mbar_wait(mbar0, (uint32_t)(li0 & 1)); li0++;        // part2 in S0
        if (warp >= 4) {  // warps 4-7 own reg rows 16-31
            #pragma unroll
            for (int r = 0; r < 4; r++)
                #pragma unroll
                for (int j = 0; j < 8; j++)
                    Wreg[r][j] = S0f4[((warp - 4) * 4 + r) * 256 + j * 32 + lane];
        }
        mbar_wait(mbar1, (uint32_t)(li1 & 1)); li1++;        // smem half in S1
        __syncthreads();                                     // S0 free, S1 + P ready
        if (tid == 0 && bi + 1 < BPG) {
            const char* gn = (const char*)(W + ((size_t)(b + 1) * NN + base) * NN);
            issue_chunks(S0a, gn, 65536, mbar0);             // next part1, flies during iters
        }

        // ---------- iterations ----------
        const float4* S1w = S1f4 + (size_t)(warp * 4) * 256; // this warp's 4 smem rows
        for (int t = 1; t <= NITERS; t++) {
            float* ys = (t & 1) ? y_s1 : y_s0;
            settle4(&g_ybuf[(t - 1) & 1][b][0], (unsigned)t, ys, tid);
            __syncthreads();
            const float4* Y4 = (const float4*)ys;

            float ar0 = 0.f, ar1 = 0.f, ar2 = 0.f, ar3 = 0.f;
            float as0 = 0.f, as1 = 0.f, as2 = 0.f, as3 = 0.f;
            #pragma unroll
            for (int j = 0; j < 8; j++) {
                const float4 y4 = Y4[j * 32 + lane];
                float4 w;
                w = Wreg[0][j];           ar0 += w.x*y4.x; ar0 += w.y*y4.y; ar0 += w.z*y4.z; ar0 += w.w*y4.w;
                w = Wreg[1][j];           ar1 += w.x*y4.x; ar1 += w.y*y4.y; ar1 += w.z*y4.z; ar1 += w.w*y4.w;
                w = Wreg[2][j];           ar2 += w.x*y4.x; ar2 += w.y*y4.y; ar2 += w.z*y4.z; ar2 += w.w*y4.w;
                w = Wreg[3][j];           ar3 += w.x*y4.x; ar3 += w.y*y4.y; ar3 += w.z*y4.z; ar3 += w.w*y4.w;
                w = S1w[0 * 256 + j * 32 + lane]; as0 += w.x*y4.x; as0 += w.y*y4.y; as0 += w.z*y4.z; as0 += w.w*y4.w;
                w = S1w[1 * 256 + j * 32 + lane]; as1 += w.x*y4.x; as1 += w.y*y4.y; as1 += w.z*y4.z; as1 += w.w*y4.w;
                w = S1w[2 * 256 + j * 32 + lane]; as2 += w.x*y4.x; as2 += w.y*y4.y; as2 += w.z*y4.z; as2 += w.w*y4.w;
                w = S1w[3 * 256 + j * 32 + lane]; as3 += w.x*y4.x; as3 += w.y*y4.y; as3 += w.z*y4.z; as3 += w.w*y4.w;
            }
            #pragma unroll
            for (int off = 16; off > 0; off >>= 1) {
                ar0 += __shfl_xor_sync(0xffffffffu, ar0, off);
                ar1 += __shfl_xor_sync(0xffffffffu, ar1, off);
                ar2 += __shfl_xor_sync(0xffffffffu, ar2, off);
                ar3 += __shfl_xor_sync(0xffffffffu, ar3, off);
                as0 += __shfl_xor_sync(0xffffffffu, as0, off);
                as1 += __shfl_xor_sync(0xffffffffu, as1, off);
                as2 += __shfl_xor_sync(0xffffffffu, as2, off);
                as3 += __shfl_xor_sync(0xffffffffu, as3, off);
            }

            if (lane < 8) {
                float dot;
                int rloc;
                if (lane < 4) {
                    dot  = (lane == 0) ? ar0 : (lane == 1) ? ar1 : (lane == 2) ? ar2 : ar3;
                    rloc = warp * 4 + lane;
                } else {
                    dot  = (lane == 4) ? as0 : (lane == 5) ? as1 : (lane == 6) ? as2 : as3;
                    rloc = 32 + warp * 4 + (lane - 4);
                }
                float v  = P[0 * 64 + rloc];
                float nv = (v + P[1 * 64 + rloc] * (dot + P[2 * 64 + rloc] - v)) * P[5 * 64 + rloc];
                P[0 * 64 + rloc] = nv;
                float ov = (t < NITERS)
                    ? tanhf(P[3 * 64 + rloc] * (nv + P[4 * 64 + rloc])) * P[5 * 64 + rloc]
                    : nv;
                stcg64(&g_ybuf[t & 1][b][base + rloc],
                       ((u64)(unsigned)(t + 1) << 32) | (u64)__float_as_uint(ov));
            }
        }

        // ---------- decode: every CTA produces one action ----------
        settle4(&g_ybuf[NITERS & 1][b][0], (unsigned)(NITERS + 1), y_s0, tid);
        __syncthreads();
        {
            const float* Dr = D + ((size_t)b * NACT + cig) * NN;
            float p = 0.f;
            for (int i = tid; i < NN; i += NTHREADS) p += Dr[i] * y_s0[i];
            #pragma unroll
            for (int off = 16; off > 0; off >>= 1)
                p += __shfl_xor_sync(0xffffffffu, p, off);
            if (lane == 0) red_s[warp] = p;
            __syncthreads();
            if (tid == 0) {
                float s = 0.f;
                #pragma unroll
                for (int j = 0; j < 8; j++) s += red_s[j];
                out[b * NACT + cig] = s;
            }
        }
        __syncthreads();   // y_s0 / red_s / P free for next batch
    }
}

extern "C" void kernel_launch(void* const* d_in, const int* in_sizes, int n_in,
                              void* d_out, int out_size) {
    const float* obs  = (const float*)d_in[0];
    const float* v0   = (const float*)d_in[1];
    const float* tau  = (const float*)d_in[2];
    const float* gain = (const float*)d_in[3];
    const float* bias = (const float*)d_in[4];
    const float* W    = (const float*)d_in[5];
    const float* mask = (const float*)d_in[6];
    const float* E    = (const float*)d_in[7];
    const float* D    = (const float*)d_in[8];
    float* out = (float*)d_out;

    cudaFuncSetAttribute(ctrnn_kernel,
                         cudaFuncAttributeMaxDynamicSharedMemorySize, SMEM_BYTES);

    // reset exchange tags each launch (tag-freshness invariant, graph-replay safe)
    ctrnn_init_kernel<<<(2 * BATCH * NN + 255) / 256, 256>>>();

    // 128 CTAs = 8 groups x 16; ~202 KB smem each -> 1 CTA/SM, all co-resident
    ctrnn_kernel<<<GROUPS * CPB, NTHREADS, SMEM_BYTES>>>(
        obs, v0, tau, gain, bias, W, mask, E, D, out);
}

// round 14
// speedup vs baseline: 3.2635x; 1.0122x over previous
#include <cuda_runtime.h>
#include <cstdint>

typedef unsigned long long u64;

#define DT_F      0.1f
#define NITERS    9               // int(1.0 // 0.1) == 9 in Python float semantics!
#define BATCH     64
#define NN        1024
#define NOBS      64
#define NACT      16
#define GROUPS    8               // groups of 16 CTAs; one batch at a time per group
#define CPB       16              // CTAs per batch
#define ROWS_CTA  64              // rows per CTA (32 in regs + 32 in smem)
#define BPG       (BATCH / GROUPS)   // 8 batches per group
#define NTHREADS  256

// y-exchange: 8-byte words = (tag<<32)|float_bits; y_t carries tag t+1, in buf[t&1].
__device__ u64 g_ybuf[2][BATCH][NN];

__global__ void ctrnn_init_kernel() {
    int i = blockIdx.x * blockDim.x + threadIdx.x;
    if (i < 2 * BATCH * NN) ((u64*)g_ybuf)[i] = 0ull;   // tag 0 = invalid
}

__device__ __forceinline__ u64 ldcg64(const u64* p) {
    u64 v;
    asm volatile("ld.global.cg.u64 %0, [%1];" : "=l"(v) : "l"(p));
    return v;
}
__device__ __forceinline__ void stcg64(u64* p, u64 v) {
    asm volatile("st.global.cg.u64 [%0], %1;" :: "l"(p), "l"(v) : "memory");
}

// packed f32x2 FMA: acc += a * b (elementwise on both 32-bit halves)
__device__ __forceinline__ void ffma2(u64& acc, u64 a, u64 b) {
    asm volatile("fma.rn.f32x2 %0, %1, %2, %0;" : "+l"(acc) : "l"(a), "l"(b));
}
__device__ __forceinline__ float unpack_sum(u64 acc) {
    float lo, hi;
    asm("mov.b64 {%0,%1}, %2;" : "=f"(lo), "=f"(hi) : "l"(acc));
    return lo + hi;
}

// gather 1024 tagged words (4/thread, strided 256).
// PARALLEL retry: every round re-issues ALL stale words concurrently.
__device__ __forceinline__ void settle4(const u64* src, unsigned exp, float* y_s, int tid) {
    u64 r0 = ldcg64(src + tid);
    u64 r1 = ldcg64(src + tid + 256);
    u64 r2 = ldcg64(src + tid + 512);
    u64 r3 = ldcg64(src + tid + 768);
    for (;;) {
        const bool s0 = (unsigned)(r0 >> 32) != exp;
        const bool s1 = (unsigned)(r1 >> 32) != exp;
        const bool s2 = (unsigned)(r2 >> 32) != exp;
        const bool s3 = (unsigned)(r3 >> 32) != exp;
        if (!(s0 | s1 | s2 | s3)) break;
        __nanosleep(30);
        if (s0) r0 = ldcg64(src + tid);
        if (s1) r1 = ldcg64(src + tid + 256);
        if (s2) r2 = ldcg64(src + tid + 512);
        if (s3) r3 = ldcg64(src + tid + 768);
    }
    y_s[tid]       = __uint_as_float((unsigned)(r0 & 0xffffffffu));
    y_s[tid + 256] = __uint_as_float((unsigned)(r1 & 0xffffffffu));
    y_s[tid + 512] = __uint_as_float((unsigned)(r2 & 0xffffffffu));
    y_s[tid + 768] = __uint_as_float((unsigned)(r3 & 0xffffffffu));
}

__device__ __forceinline__ void mbar_init(uint32_t a, uint32_t cnt) {
    asm volatile("mbarrier.init.shared.b64 [%0], %1;" :: "r"(a), "r"(cnt) : "memory");
}
__device__ __forceinline__ void mbar_expect_tx(uint32_t a, uint32_t bytes) {
    asm volatile("mbarrier.arrive.expect_tx.shared.b64 _, [%0], %1;" :: "r"(a), "r"(bytes) : "memory");
}
__device__ __forceinline__ void mbar_wait(uint32_t a, uint32_t parity) {
    asm volatile(
        "{\n\t.reg .pred P;\n\t"
        "W_%=:\n\t"
        "mbarrier.try_wait.parity.shared.b64 P, [%0], %1;\n\t"
        "@P bra.uni D_%=;\n\t"
        "bra.uni W_%=;\n\t"
        "D_%=:\n\t}"
        :: "r"(a), "r"(parity) : "memory");
}
__device__ __forceinline__ void bulk_g2s(uint32_t dst, const void* src, uint32_t bytes, uint32_t mbar) {
    asm volatile(
        "cp.async.bulk.shared::cta.global.mbarrier::complete_tx::bytes [%0], [%1], %2, [%3];"
        :: "r"(dst), "l"(src), "r"(bytes), "r"(mbar) : "memory");
}
__device__ __forceinline__ void issue_chunks(uint32_t dst, const char* gsrc,
                                             uint32_t bytes, uint32_t mbar) {
    asm volatile("fence.proxy.async.shared::cta;" ::: "memory");
    mbar_expect_tx(mbar, bytes);
    for (uint32_t c = 0; c < bytes; c += 32768)
        bulk_g2s(dst + c, gsrc + c, 32768, mbar);
}

// SMEM layout (bytes):
//   S1 (smem W half, 32 rows)   : [0, 131072)
//   S0 (staging, 16 rows)       : [131072, 196608)
//   y_s[2][1024]                : [196608, 204800)
//   P[6][64]                    : [204800, 206336)
//   obs_s[64]                   : [206336, 206592)
//   red_s[8]                    : [206592, 206624)
//   mbar0, mbar1                : [206624, 206640)
#define S1_OFF    0
#define S0_OFF    131072
#define YS_OFF    196608
#define P_OFF     204800
#define OBS_OFF   206336
#define RED_OFF   206592
#define MB_OFF    206624
#define SMEM_BYTES 206640

__global__ __launch_bounds__(NTHREADS, 1)
void ctrnn_kernel(const float* __restrict__ obs,  const float* __restrict__ v0,
                  const float* __restrict__ tau,  const float* __restrict__ gain,
                  const float* __restrict__ bias, const float* __restrict__ W,
                  const float* __restrict__ mask, const float* __restrict__ E,
                  const float* __restrict__ D,    float* __restrict__ out)
{
    extern __shared__ char sm[];
    ulonglong2* S1v2 = (ulonglong2*)(sm + S1_OFF);   // 32 rows x 256 x 16B
    ulonglong2* S0v2 = (ulonglong2*)(sm + S0_OFF);   // 16 rows x 256 x 16B
    float*  y_s0  = (float*)(sm + YS_OFF);           // parity 0
    float*  y_s1  = y_s0 + NN;                       // parity 1
    float*  P     = (float*)(sm + P_OFF);            // [6][64]
    float*  obs_s = (float*)(sm + OBS_OFF);
    float*  red_s = (float*)(sm + RED_OFF);

    const int tid  = threadIdx.x;
    const int warp = tid >> 5;
    const int lane = tid & 31;
    const int group = blockIdx.x >> 4;        // /16
    const int cig   = blockIdx.x & 15;
    const int base  = cig * ROWS_CTA;         // first of this CTA's 64 rows

    const uint32_t mbar0 = (uint32_t)__cvta_generic_to_shared(sm + MB_OFF);
    const uint32_t mbar1 = mbar0 + 8;
    const uint32_t S0a   = (uint32_t)__cvta_generic_to_shared(S0v2);
    const uint32_t S1a   = (uint32_t)__cvta_generic_to_shared(S1v2);

    if (tid == 0) {
        mbar_init(mbar0, 1);
        mbar_init(mbar1, 1);
        asm volatile("fence.proxy.async.shared::cta;" ::: "memory");
    }
    __syncthreads();

    if (tid == 0) {
        const char* g = (const char*)(W + ((size_t)(group * BPG) * NN + base) * NN);
        issue_chunks(S0a, g, 65536, mbar0);              // part1 of batch 0
        issue_chunks(S1a, g + 131072, 131072, mbar1);    // smem half of batch 0
    }

    ulonglong2 Wreg[4][8];   // this warp's 4 register rows x 8 16B-chunks (f32x2 pairs)
    int li0 = 0, li1 = 0;

    for (int bi = 0; bi < BPG; bi++) {
        const int b = group * BPG + bi;
        const char* gW = (const char*)(W + ((size_t)b * NN + base) * NN);

        // ---------- batch start: assemble W ----------
        mbar_wait(mbar0, (uint32_t)(li0 & 1)); li0++;        // part1 in S0
        if (warp < 4) {   // warps 0-3 own reg rows 0-15
            #pragma unroll
            for (int r = 0; r < 4; r++)
                #pragma unroll
                for (int j = 0; j < 8; j++)
                    Wreg[r][j] = S0v2[(warp * 4 + r) * 256 + j * 32 + lane];
        }
        __syncthreads();                                     // S0 free
        if (tid == 0)
            issue_chunks(S0a, gW + 65536, 65536, mbar0);     // part2 (S1 already in flight)

        // ---------- prologue (overlaps TMA) ----------
        if (tid < NOBS) obs_s[tid] = obs[(size_t)b * NOBS + tid];
        __syncthreads();
        if (tid < ROWS_CTA) {
            const int n = base + tid;
            const size_t o = (size_t)b * NN + n;
            float vv = v0[o], gg = gain[o], bb = bias[o], mm = mask[o];
            P[0 * 64 + tid] = vv;
            P[1 * 64 + tid] = DT_F / tau[o];
            P[3 * 64 + tid] = gg;
            P[4 * 64 + tid] = bb;
            P[5 * 64 + tid] = mm;
            const float* Er = E + o * NOBS;
            float s = 0.f;
            #pragma unroll
            for (int q = 0; q < NOBS; q++) s += Er[q] * obs_s[q];
            P[2 * 64 + tid] = s;
            float y0 = tanhf(gg * (vv + bb)) * mm;
            stcg64(&g_ybuf[0][b][n], ((u64)1 << 32) | (u64)__float_as_uint(y0));
        }

        mbar_wait(mbar0, (uint32_t)(li0 & 1)); li0++;        // part2 in S0
        if (warp >= 4) {  // warps 4-7 own reg rows 16-31
            #pragma unroll
            for (int r = 0; r < 4; r++)
                #pragma unroll
                for (int j = 0; j < 8; j++)
                    Wreg[r][j] = S0v2[((warp - 4) * 4 + r) * 256 + j * 32 + lane];
        }
        mbar_wait(mbar1, (uint32_t)(li1 & 1)); li1++;        // smem half in S1
        __syncthreads();                                     // S0 free, S1 + P ready
        if (tid == 0 && bi + 1 < BPG) {
            const char* gn = (const char*)(W + ((size_t)(b + 1) * NN + base) * NN);
            issue_chunks(S0a, gn, 65536, mbar0);             // next part1, flies during iters
        }

        // ---------- iterations ----------
        const ulonglong2* S1w = S1v2 + (size_t)(warp * 4) * 256;  // this warp's 4 smem rows
        for (int t = 1; t <= NITERS; t++) {
            float* ys = (t & 1) ? y_s1 : y_s0;
            settle4(&g_ybuf[(t - 1) & 1][b][0], (unsigned)t, ys, tid);
            __syncthreads();
            const ulonglong2* Y2 = (const ulonglong2*)ys;

            u64 ar0 = 0, ar1 = 0, ar2 = 0, ar3 = 0;   // packed f32x2 accumulators
            u64 as0 = 0, as1 = 0, as2 = 0, as3 = 0;
            #pragma unroll
            for (int j = 0; j < 8; j++) {
                const ulonglong2 y2 = Y2[j * 32 + lane];
                ulonglong2 w;
                w = Wreg[0][j];                   ffma2(ar0, w.x, y2.x); ffma2(ar0, w.y, y2.y);
                w = Wreg[1][j];                   ffma2(ar1, w.x, y2.x); ffma2(ar1, w.y, y2.y);
                w = Wreg[2][j];                   ffma2(ar2, w.x, y2.x); ffma2(ar2, w.y, y2.y);
                w = Wreg[3][j];                   ffma2(ar3, w.x, y2.x); ffma2(ar3, w.y, y2.y);
                w = S1w[0 * 256 + j * 32 + lane]; ffma2(as0, w.x, y2.x); ffma2(as0, w.y, y2.y);
                w = S1w[1 * 256 + j * 32 + lane]; ffma2(as1, w.x, y2.x); ffma2(as1, w.y, y2.y);
                w = S1w[2 * 256 + j * 32 + lane]; ffma2(as2, w.x, y2.x); ffma2(as2, w.y, y2.y);
                w = S1w[3 * 256 + j * 32 + lane]; ffma2(as3, w.x, y2.x); ffma2(as3, w.y, y2.y);
            }
            float fr0 = unpack_sum(ar0), fr1 = unpack_sum(ar1);
            float fr2 = unpack_sum(ar2), fr3 = unpack_sum(ar3);
            float fs0 = unpack_sum(as0), fs1 = unpack_sum(as1);
            float fs2 = unpack_sum(as2), fs3 = unpack_sum(as3);
            #pragma unroll
            for (int off = 16; off > 0; off >>= 1) {
                fr0 += __shfl_xor_sync(0xffffffffu, fr0, off);
                fr1 += __shfl_xor_sync(0xffffffffu, fr1, off);
                fr2 += __shfl_xor_sync(0xffffffffu, fr2, off);
                fr3 += __shfl_xor_sync(0xffffffffu, fr3, off);
                fs0 += __shfl_xor_sync(0xffffffffu, fs0, off);
                fs1 += __shfl_xor_sync(0xffffffffu, fs1, off);
                fs2 += __shfl_xor_sync(0xffffffffu, fs2, off);
                fs3 += __shfl_xor_sync(0xffffffffu, fs3, off);
            }

            if (lane < 8) {
                float dot;
                int rloc;
                if (lane < 4) {
                    dot  = (lane == 0) ? fr0 : (lane == 1) ? fr1 : (lane == 2) ? fr2 : fr3;
                    rloc = warp * 4 + lane;
                } else {
                    dot  = (lane == 4) ? fs0 : (lane == 5) ? fs1 : (lane == 6) ? fs2 : fs3;
                    rloc = 32 + warp * 4 + (lane - 4);
                }
                float v  = P[0 * 64 + rloc];
                float nv = (v + P[1 * 64 + rloc] * (dot + P[2 * 64 + rloc] - v)) * P[5 * 64 + rloc];
                P[0 * 64 + rloc] = nv;
                float ov = (t < NITERS)
                    ? tanhf(P[3 * 64 + rloc] * (nv + P[4 * 64 + rloc])) * P[5 * 64 + rloc]
                    : nv;
                stcg64(&g_ybuf[t & 1][b][base + rloc],
                       ((u64)(unsigned)(t + 1) << 32) | (u64)__float_as_uint(ov));
            }
        }

        // ---------- decode: every CTA produces one action ----------
        settle4(&g_ybuf[NITERS & 1][b][0], (unsigned)(NITERS + 1), y_s0, tid);
        __syncthreads();
        // All 1024 final tags verified by this CTA's threads => every local warp
        // finished its last S1 read (publish follows the reads). S1 is free:
        // issue next batch's smem-W half NOW, hiding it under decode + prologue.
        if (tid == 0 && bi + 1 < BPG) {
            const char* gn = (const char*)(W + ((size_t)(b + 1) * NN + base) * NN);
            issue_chunks(S1a, gn + 131072, 131072, mbar1);
        }
        {
            const float* Dr = D + ((size_t)b * NACT + cig) * NN;
            float p = 0.f;
            for (int i = tid; i < NN; i += NTHREADS) p += Dr[i] * y_s0[i];
            #pragma unroll
            for (int off = 16; off > 0; off >>= 1)
                p += __shfl_xor_sync(0xffffffffu, p, off);
            if (lane == 0) red_s[warp] = p;
            __syncthreads();
            if (tid == 0) {
                float s = 0.f;
                #pragma unroll
                for (int j = 0; j < 8; j++) s += red_s[j];
                out[b * NACT + cig] = s;
            }
        }
        __syncthreads();   // y_s0 / red_s / P free for next batch
    }
}

extern "C" void kernel_launch(void* const* d_in, const int* in_sizes, int n_in,
                              void* d_out, int out_size) {
    const float* obs  = (const float*)d_in[0];
    const float* v0   = (const float*)d_in[1];
    const float* tau  = (const float*)d_in[2];
    const float* gain = (const float*)d_in[3];
    const float* bias = (const float*)d_in[4];
    const float* W    = (const float*)d_in[5];
    const float* mask = (const float*)d_in[6];
    const float* E    = (const float*)d_in[7];
    const float* D    = (const float*)d_in[8];
    float* out = (float*)d_out;

    cudaFuncSetAttribute(ctrnn_kernel,
                         cudaFuncAttributeMaxDynamicSharedMemorySize, SMEM_BYTES);

    // reset exchange tags each launch (tag-freshness invariant, graph-replay safe)
    ctrnn_init_kernel<<<(2 * BATCH * NN + 255) / 256, 256>>>();

    // 128 CTAs = 8 groups x 16; ~202 KB smem each -> 1 CTA/SM, all co-resident
    ctrnn_kernel<<<GROUPS * CPB, NTHREADS, SMEM_BYTES>>>(
        obs, v0, tau, gain, bias, W, mask, E, D, out);
}

// round 15
// speedup vs baseline: 3.3559x; 1.0283x over previous
#include <cuda_runtime.h>
#include <cstdint>

typedef unsigned long long u64;

#define DT_F      0.1f
#define NITERS    9               // int(1.0 // 0.1) == 9 in Python float semantics!
#define BATCH     64
#define NN        1024
#define NOBS      64
#define NACT      16
#define GROUPS    8               // groups of 16 CTAs; one batch at a time per group
#define CPB       16              // CTAs per batch
#define ROWS_CTA  64              // rows per CTA (32 in regs + 32 in smem)
#define BPG       (BATCH / GROUPS)   // 8 batches per group
#define NTHREADS  256

// y-exchange: 8-byte words = (tag<<32)|float_bits; y_t carries tag t+1, in buf[t&1].
__device__ u64 g_ybuf[2][BATCH][NN];

__global__ void ctrnn_init_kernel() {
    int i = blockIdx.x * blockDim.x + threadIdx.x;
    if (i < 2 * BATCH * NN) ((u64*)g_ybuf)[i] = 0ull;   // tag 0 = invalid
}

__device__ __forceinline__ u64 ldcg64(const u64* p) {
    u64 v;
    asm volatile("ld.global.cg.u64 %0, [%1];" : "=l"(v) : "l"(p));
    return v;
}
__device__ __forceinline__ void stcg64(u64* p, u64 v) {
    asm volatile("st.global.cg.u64 [%0], %1;" :: "l"(p), "l"(v) : "memory");
}

// packed f32x2 FMA: acc += a * b (elementwise on both 32-bit halves)
__device__ __forceinline__ void ffma2(u64& acc, u64 a, u64 b) {
    asm volatile("fma.rn.f32x2 %0, %1, %2, %0;" : "+l"(acc) : "l"(a), "l"(b));
}
__device__ __forceinline__ float unpack_sum(u64 acc) {
    float lo, hi;
    asm("mov.b64 {%0,%1}, %2;" : "=f"(lo), "=f"(hi) : "l"(acc));
    return lo + hi;
}

// verify ONE pair of tagged words (parallel retry), commit to y_s
__device__ __forceinline__ void settle_pair(const u64* src, unsigned exp, float* y_s,
                                            int tid, int o1, int o2, u64& a, u64& c) {
    for (;;) {
        const bool s0 = (unsigned)(a >> 32) != exp;
        const bool s1 = (unsigned)(c >> 32) != exp;
        if (!(s0 | s1)) break;
        __nanosleep(30);
        if (s0) a = ldcg64(src + tid + o1);
        if (s1) c = ldcg64(src + tid + o2);
    }
    y_s[tid + o1] = __uint_as_float((unsigned)(a & 0xffffffffu));
    y_s[tid + o2] = __uint_as_float((unsigned)(c & 0xffffffffu));
}

// full 1024-word settle (used for the final/decode gather)
__device__ __forceinline__ void settle4(const u64* src, unsigned exp, float* y_s, int tid) {
    u64 r0 = ldcg64(src + tid);
    u64 r1 = ldcg64(src + tid + 256);
    u64 r2 = ldcg64(src + tid + 512);
    u64 r3 = ldcg64(src + tid + 768);
    for (;;) {
        const bool s0 = (unsigned)(r0 >> 32) != exp;
        const bool s1 = (unsigned)(r1 >> 32) != exp;
        const bool s2 = (unsigned)(r2 >> 32) != exp;
        const bool s3 = (unsigned)(r3 >> 32) != exp;
        if (!(s0 | s1 | s2 | s3)) break;
        __nanosleep(30);
        if (s0) r0 = ldcg64(src + tid);
        if (s1) r1 = ldcg64(src + tid + 256);
        if (s2) r2 = ldcg64(src + tid + 512);
        if (s3) r3 = ldcg64(src + tid + 768);
    }
    y_s[tid]       = __uint_as_float((unsigned)(r0 & 0xffffffffu));
    y_s[tid + 256] = __uint_as_float((unsigned)(r1 & 0xffffffffu));
    y_s[tid + 512] = __uint_as_float((unsigned)(r2 & 0xffffffffu));
    y_s[tid + 768] = __uint_as_float((unsigned)(r3 & 0xffffffffu));
}

__device__ __forceinline__ void mbar_init(uint32_t a, uint32_t cnt) {
    asm volatile("mbarrier.init.shared.b64 [%0], %1;" :: "r"(a), "r"(cnt) : "memory");
}
__device__ __forceinline__ void mbar_expect_tx(uint32_t a, uint32_t bytes) {
    asm volatile("mbarrier.arrive.expect_tx.shared.b64 _, [%0], %1;" :: "r"(a), "r"(bytes) : "memory");
}
__device__ __forceinline__ void mbar_wait(uint32_t a, uint32_t parity) {
    asm volatile(
        "{\n\t.reg .pred P;\n\t"
        "W_%=:\n\t"
        "mbarrier.try_wait.parity.shared.b64 P, [%0], %1;\n\t"
        "@P bra.uni D_%=;\n\t"
        "bra.uni W_%=;\n\t"
        "D_%=:\n\t}"
        :: "r"(a), "r"(parity) : "memory");
}
__device__ __forceinline__ void bulk_g2s(uint32_t dst, const void* src, uint32_t bytes, uint32_t mbar) {
    asm volatile(
        "cp.async.bulk.shared::cta.global.mbarrier::complete_tx::bytes [%0], [%1], %2, [%3];"
        :: "r"(dst), "l"(src), "r"(bytes), "r"(mbar) : "memory");
}
__device__ __forceinline__ void issue_chunks(uint32_t dst, const char* gsrc,
                                             uint32_t bytes, uint32_t mbar) {
    asm volatile("fence.proxy.async.shared::cta;" ::: "memory");
    mbar_expect_tx(mbar, bytes);
    for (uint32_t c = 0; c < bytes; c += 32768)
        bulk_g2s(dst + c, gsrc + c, 32768, mbar);
}

// SMEM layout (bytes):
//   S1 (smem W half, 32 rows)   : [0, 131072)
//   S0 (staging, 16 rows)       : [131072, 196608)
//   y_s[2][1024]                : [196608, 204800)
//   P[2][6][64]                 : [204800, 207872)   (double-buffered params)
//   obs_s[64]                   : [207872, 208128)
//   red_s[8]                    : [208128, 208160)
//   mbar0, mbar1                : [208160, 208176)
#define S1_OFF    0
#define S0_OFF    131072
#define YS_OFF    196608
#define P_OFF     204800
#define OBS_OFF   207872
#define RED_OFF   208128
#define MB_OFF    208160
#define SMEM_BYTES 208176

__global__ __launch_bounds__(NTHREADS, 1)
void ctrnn_kernel(const float* __restrict__ obs,  const float* __restrict__ v0,
                  const float* __restrict__ tau,  const float* __restrict__ gain,
                  const float* __restrict__ bias, const float* __restrict__ W,
                  const float* __restrict__ mask, const float* __restrict__ E,
                  const float* __restrict__ D,    float* __restrict__ out)
{
    extern __shared__ char sm[];
    ulonglong2* S1v2 = (ulonglong2*)(sm + S1_OFF);   // 32 rows x 256 x 16B
    ulonglong2* S0v2 = (ulonglong2*)(sm + S0_OFF);   // 16 rows x 256 x 16B
    float*  y_s0  = (float*)(sm + YS_OFF);           // parity 0
    float*  y_s1  = y_s0 + NN;                       // parity 1
    float*  Pbuf  = (float*)(sm + P_OFF);            // [2][6][64]
    float*  obs_s = (float*)(sm + OBS_OFF);
    float*  red_s = (float*)(sm + RED_OFF);

    const int tid  = threadIdx.x;
    const int warp = tid >> 5;
    const int lane = tid & 31;
    const int group = blockIdx.x >> 4;        // /16
    const int cig   = blockIdx.x & 15;
    const int base  = cig * ROWS_CTA;         // first of this CTA's 64 rows

    const uint32_t mbar0 = (uint32_t)__cvta_generic_to_shared(sm + MB_OFF);
    const uint32_t mbar1 = mbar0 + 8;
    const uint32_t S0a   = (uint32_t)__cvta_generic_to_shared(S0v2);
    const uint32_t S1a   = (uint32_t)__cvta_generic_to_shared(S1v2);

    if (tid == 0) {
        mbar_init(mbar0, 1);
        mbar_init(mbar1, 1);
        asm volatile("fence.proxy.async.shared::cta;" ::: "memory");
    }
    __syncthreads();

    if (tid == 0) {
        const char* g = (const char*)(W + ((size_t)(group * BPG) * NN + base) * NN);
        issue_chunks(S0a, g, 65536, mbar0);              // part1 of batch 0
        issue_chunks(S1a, g + 131072, 131072, mbar1);    // smem half of batch 0
    }

    // ---- batch 0 prologue (params -> P[0], publish y0 tag 1) ----
    {
        const int b0 = group * BPG;
        if (tid < NOBS) obs_s[tid] = obs[(size_t)b0 * NOBS + tid];
        __syncthreads();
        if (tid < ROWS_CTA) {
            float* Pn = Pbuf;                            // parity 0
            const int n = base + tid;
            const size_t o = (size_t)b0 * NN + n;
            float vv = v0[o], gg = gain[o], bb = bias[o], mm = mask[o];
            Pn[0 * 64 + tid] = vv;
            Pn[1 * 64 + tid] = DT_F / tau[o];
            Pn[3 * 64 + tid] = gg;
            Pn[4 * 64 + tid] = bb;
            Pn[5 * 64 + tid] = mm;
            const float* Er = E + o * NOBS;
            float s = 0.f;
            #pragma unroll
            for (int q = 0; q < NOBS; q++) s += Er[q] * obs_s[q];
            Pn[2 * 64 + tid] = s;
            float y0 = tanhf(gg * (vv + bb)) * mm;
            stcg64(&g_ybuf[0][b0][n], ((u64)1 << 32) | (u64)__float_as_uint(y0));
        }
    }

    ulonglong2 Wreg[4][8];   // this warp's 4 register rows x 8 16B-chunks
    int li0 = 0, li1 = 0;

    for (int bi = 0; bi < BPG; bi++) {
        const int b = group * BPG + bi;
        const char* gW = (const char*)(W + ((size_t)b * NN + base) * NN);
        float* Pc = Pbuf + (bi & 1) * 384;               // current params

        // ---------- batch start: assemble W ----------
        mbar_wait(mbar0, (uint32_t)(li0 & 1)); li0++;    // part1 in S0
        if (warp < 4) {
            #pragma unroll
            for (int r = 0; r < 4; r++)
                #pragma unroll
                for (int j = 0; j < 8; j++)
                    Wreg[r][j] = S0v2[(warp * 4 + r) * 256 + j * 32 + lane];
        }
        __syncthreads();                                 // S0 free
        if (tid == 0)
            issue_chunks(S0a, gW + 65536, 65536, mbar0); // part2 (S1 already in flight)

        mbar_wait(mbar0, (uint32_t)(li0 & 1)); li0++;    // part2 in S0
        if (warp >= 4) {
            #pragma unroll
            for (int r = 0; r < 4; r++)
                #pragma unroll
                for (int j = 0; j < 8; j++)
                    Wreg[r][j] = S0v2[((warp - 4) * 4 + r) * 256 + j * 32 + lane];
        }
        mbar_wait(mbar1, (uint32_t)(li1 & 1)); li1++;    // smem half in S1
        __syncthreads();                                 // S0 free, S1 + P ready
        if (tid == 0 && bi + 1 < BPG) {
            const char* gn = (const char*)(W + ((size_t)(b + 1) * NN + base) * NN);
            issue_chunks(S0a, gn, 65536, mbar0);         // next part1, flies during iters
        }

        // ---------- iterations (split-settle pipelined) ----------
        const ulonglong2* S1w = S1v2 + (size_t)(warp * 4) * 256;
        for (int t = 1; t <= NITERS; t++) {
            float* ys = (t & 1) ? y_s1 : y_s0;
            const u64* src = &g_ybuf[(t - 1) & 1][b][0];
            const unsigned exp = (unsigned)t;
            // issue ALL loads up-front (MLP), verify in halves
            u64 r0 = ldcg64(src + tid);
            u64 r1 = ldcg64(src + tid + 256);
            u64 r2 = ldcg64(src + tid + 512);
            u64 r3 = ldcg64(src + tid + 768);

            settle_pair(src, exp, ys, tid, 0, 256, r0, r1);
            __syncthreads();                             // y[0:512] ready
            const ulonglong2* Y2 = (const ulonglong2*)ys;

            u64 ar0 = 0, ar1 = 0, ar2 = 0, ar3 = 0;
            u64 as0 = 0, as1 = 0, as2 = 0, as3 = 0;
            #pragma unroll
            for (int j = 0; j < 4; j++) {                // first half: y[0:512]
                const ulonglong2 y2 = Y2[j * 32 + lane];
                ulonglong2 w;
                w = Wreg[0][j];                   ffma2(ar0, w.x, y2.x); ffma2(ar0, w.y, y2.y);
                w = Wreg[1][j];                   ffma2(ar1, w.x, y2.x); ffma2(ar1, w.y, y2.y);
                w = Wreg[2][j];                   ffma2(ar2, w.x, y2.x); ffma2(ar2, w.y, y2.y);
                w = Wreg[3][j];                   ffma2(ar3, w.x, y2.x); ffma2(ar3, w.y, y2.y);
                w = S1w[0 * 256 + j * 32 + lane]; ffma2(as0, w.x, y2.x); ffma2(as0, w.y, y2.y);
                w = S1w[1 * 256 + j * 32 + lane]; ffma2(as1, w.x, y2.x); ffma2(as1, w.y, y2.y);
                w = S1w[2 * 256 + j * 32 + lane]; ffma2(as2, w.x, y2.x); ffma2(as2, w.y, y2.y);
                w = S1w[3 * 256 + j * 32 + lane]; ffma2(as3, w.x, y2.x); ffma2(as3, w.y, y2.y);
            }

            settle_pair(src, exp, ys, tid, 512, 768, r2, r3);
            __syncthreads();                             // y[512:1024] ready

            #pragma unroll
            for (int j = 4; j < 8; j++) {                // second half
                const ulonglong2 y2 = Y2[j * 32 + lane];
                ulonglong2 w;
                w = Wreg[0][j];                   ffma2(ar0, w.x, y2.x); ffma2(ar0, w.y, y2.y);
                w = Wreg[1][j];                   ffma2(ar1, w.x, y2.x); ffma2(ar1, w.y, y2.y);
                w = Wreg[2][j];                   ffma2(ar2, w.x, y2.x); ffma2(ar2, w.y, y2.y);
                w = Wreg[3][j];                   ffma2(ar3, w.x, y2.x); ffma2(ar3, w.y, y2.y);
                w = S1w[0 * 256 + j * 32 + lane]; ffma2(as0, w.x, y2.x); ffma2(as0, w.y, y2.y);
                w = S1w[1 * 256 + j * 32 + lane]; ffma2(as1, w.x, y2.x); ffma2(as1, w.y, y2.y);
                w = S1w[2 * 256 + j * 32 + lane]; ffma2(as2, w.x, y2.x); ffma2(as2, w.y, y2.y);
                w = S1w[3 * 256 + j * 32 + lane]; ffma2(as3, w.x, y2.x); ffma2(as3, w.y, y2.y);
            }

            float fr0 = unpack_sum(ar0), fr1 = unpack_sum(ar1);
            float fr2 = unpack_sum(ar2), fr3 = unpack_sum(ar3);
            float fs0 = unpack_sum(as0), fs1 = unpack_sum(as1);
            float fs2 = unpack_sum(as2), fs3 = unpack_sum(as3);
            #pragma unroll
            for (int off = 16; off > 0; off >>= 1) {
                fr0 += __shfl_xor_sync(0xffffffffu, fr0, off);
                fr1 += __shfl_xor_sync(0xffffffffu, fr1, off);
                fr2 += __shfl_xor_sync(0xffffffffu, fr2, off);
                fr3 += __shfl_xor_sync(0xffffffffu, fr3, off);
                fs0 += __shfl_xor_sync(0xffffffffu, fs0, off);
                fs1 += __shfl_xor_sync(0xffffffffu, fs1, off);
                fs2 += __shfl_xor_sync(0xffffffffu, fs2, off);
                fs3 += __shfl_xor_sync(0xffffffffu, fs3, off);
            }

            if (lane < 8) {
                float dot;
                int rloc;
                if (lane < 4) {
                    dot  = (lane == 0) ? fr0 : (lane == 1) ? fr1 : (lane == 2) ? fr2 : fr3;
                    rloc = warp * 4 + lane;
                } else {
                    dot  = (lane == 4) ? fs0 : (lane == 5) ? fs1 : (lane == 6) ? fs2 : fs3;
                    rloc = 32 + warp * 4 + (lane - 4);
                }
                float v  = Pc[0 * 64 + rloc];
                float nv = (v + Pc[1 * 64 + rloc] * (dot + Pc[2 * 64 + rloc] - v)) * Pc[5 * 64 + rloc];
                Pc[0 * 64 + rloc] = nv;
                float ov = (t < NITERS)
                    ? tanhf(Pc[3 * 64 + rloc] * (nv + Pc[4 * 64 + rloc])) * Pc[5 * 64 + rloc]
                    : nv;
                stcg64(&g_ybuf[t & 1][b][base + rloc],
                       ((u64)(unsigned)(t + 1) << 32) | (u64)__float_as_uint(ov));
            }
        }

        // ---------- merged boundary: decode + next-batch prologue ----------
        // prefetch this CTA's D row (independent of the settle)
        const float4 dv = ((const float4*)(D + ((size_t)b * NACT + cig) * NN))[tid];
        settle4(&g_ybuf[NITERS & 1][b][0], (unsigned)(NITERS + 1), y_s0, tid);
        __syncthreads();
        // S1 free (all local publishes done => all S1 reads done): prefetch next smem half
        if (tid == 0 && bi + 1 < BPG) {
            const char* gn = (const char*)(W + ((size_t)(b + 1) * NN + base) * NN);
            issue_chunks(S1a, gn + 131072, 131072, mbar1);
        }
        // decode partial dot from prefetched D registers
        {
            float p = dv.x * y_s0[4 * tid]     + dv.y * y_s0[4 * tid + 1]
                    + dv.z * y_s0[4 * tid + 2] + dv.w * y_s0[4 * tid + 3];
            #pragma unroll
            for (int off = 16; off > 0; off >>= 1)
                p += __shfl_xor_sync(0xffffffffu, p, off);
            if (lane == 0) red_s[warp] = p;
        }
        // next-batch prologue (independent global loads, same latency window)
        float vv = 0.f, gg = 0.f, bb = 0.f, mm = 0.f;
        if (bi + 1 < BPG) {
            if (tid < NOBS) obs_s[tid] = obs[(size_t)(b + 1) * NOBS + tid];
            if (tid < ROWS_CTA) {
                float* Pn = Pbuf + ((bi + 1) & 1) * 384;
                const size_t o = (size_t)(b + 1) * NN + (base + tid);
                vv = v0[o]; gg = gain[o]; bb = bias[o]; mm = mask[o];
                Pn[0 * 64 + tid] = vv;
                Pn[1 * 64 + tid] = DT_F / tau[o];
                Pn[3 * 64 + tid] = gg;
                Pn[4 * 64 + tid] = bb;
                Pn[5 * 64 + tid] = mm;
            }
        }
        __syncthreads();   // red_s + obs_s ready
        if (tid == 0) {
            float s = 0.f;
            #pragma unroll
            for (int j = 0; j < 8; j++) s += red_s[j];
            out[b * NACT + cig] = s;
        }
        if (bi + 1 < BPG && tid < ROWS_CTA) {
            float* Pn = Pbuf + ((bi + 1) & 1) * 384;
            const int n = base + tid;
            const float* Er = E + ((size_t)(b + 1) * NN + n) * NOBS;
            float s = 0.f;
            #pragma unroll
            for (int q = 0; q < NOBS; q++) s += Er[q] * obs_s[q];
            Pn[2 * 64 + tid] = s;
            float y0 = tanhf(gg * (vv + bb)) * mm;
            stcg64(&g_ybuf[0][b + 1][n], ((u64)1 << 32) | (u64)__float_as_uint(y0));
        }
        __syncthreads();   // Pn / y_s0 safe before next batch
    }
}

extern "C" void kernel_launch(void* const* d_in, const int* in_sizes, int n_in,
                              void* d_out, int out_size) {
    const float* obs  = (const float*)d_in[0];
    const float* v0   = (const float*)d_in[1];
    const float* tau  = (const float*)d_in[2];
    const float* gain = (const float*)d_in[3];
    const float* bias = (const float*)d_in[4];
    const float* W    = (const float*)d_in[5];
    const float* mask = (const float*)d_in[6];
    const float* E    = (const float*)d_in[7];
    const float* D    = (const float*)d_in[8];
    float* out = (float*)d_out;

    cudaFuncSetAttribute(ctrnn_kernel,
                         cudaFuncAttributeMaxDynamicSharedMemorySize, SMEM_BYTES);

    // reset exchange tags each launch (tag-freshness invariant, graph-replay safe)
    ctrnn_init_kernel<<<(2 * BATCH * NN + 255) / 256, 256>>>();

    // 128 CTAs = 8 groups x 16; ~203 KB smem each -> 1 CTA/SM, all co-resident
    ctrnn_kernel<<<GROUPS * CPB, NTHREADS, SMEM_BYTES>>>(
        obs, v0, tau, gain, bias, W, mask, E, D, out);
}